// round 5
// baseline (speedup 1.0000x reference)
#include <cuda_runtime.h>
#include <cuda_bf16.h>
#include <stdint.h>

#define GN 512
#define GW 332
#define GH 324
#define GHW (GW * GH)
#define GC 120
#define TSX 16
#define TSY 4
#define NROWS 81   // GH / TSY

// packed compact gaussian params (depth-sorted, valid only)
__device__ float4 g_pk1[GN];   // gx, gy, c00, c11
__device__ float4 g_pk2[GN];   // op, depth, sid (as float bits), rx
__device__ int    g_cnt;
__device__ int    g_rowcnt[NROWS];
__device__ int    g_rowlist[NROWS][GN];

static __device__ __forceinline__ unsigned order_float(float f) {
    unsigned u = __float_as_uint(f);
    return (u & 0x80000000u) ? ~u : (u | 0x80000000u);
}

// ---------------------------------------------------------------------------
// Kernel 1: project, validity, cinv, stable depth sort, compact, row-bin.
// One block, 512 threads.
// ---------------------------------------------------------------------------
__global__ __launch_bounds__(GN) void prep_kernel(
    const float* __restrict__ pos,     // [N,3]
    const float* __restrict__ scales,  // [N,3]
    const float* __restrict__ ops,     // [N]
    const float* __restrict__ K,       // [3,3]
    const float* __restrict__ E)       // [4,4]
{
    __shared__ float s_gx[GN], s_gy[GN], s_c00[GN], s_c11[GN], s_op[GN], s_dep[GN];
    __shared__ unsigned char s_valid[GN];
    __shared__ unsigned long long s_key[GN];
    __shared__ int s_wcnt[16];
    __shared__ int s_tot;

    const int i = threadIdx.x;

    float p0 = pos[3 * i + 0], p1 = pos[3 * i + 1], p2 = pos[3 * i + 2];
    float cx = E[0] * p0 + E[1] * p1 + E[2]  * p2 + E[3];
    float cy = E[4] * p0 + E[5] * p1 + E[6]  * p2 + E[7];
    float cz = E[8] * p0 + E[9] * p1 + E[10] * p2 + E[11];
    float prx = K[0] * cx + K[1] * cy + K[2] * cz;
    float pry = K[3] * cx + K[4] * cy + K[5] * cz;
    float prz = K[6] * cx + K[7] * cy + K[8] * cz;
    float sx = prx / (prz + 1e-6f);
    float sy = pry / (prz + 1e-6f);
    float d  = cz;

    bool valid = (d > 0.01f) && (d < 100.0f) &&
                 (sx > -100.0f) && (sx < (float)GW + 100.0f) &&
                 (sy > -100.0f) && (sy < (float)GH + 100.0f);

    float s0 = scales[3 * i + 0], s1 = scales[3 * i + 1];
    s_gx[i]  = sx;
    s_gy[i]  = sy;
    s_c00[i] = 1.0f / (s0 * s0 + 1e-4f);
    s_c11[i] = 1.0f / (s1 * s1 + 1e-4f);
    s_op[i]  = ops[i];
    s_dep[i] = d;
    s_valid[i] = valid ? 1 : 0;
    s_key[i] = ((unsigned long long)order_float(d) << 32) | (unsigned)i;
    __syncthreads();

    // Bitonic sort 512 keys ascending (depth, then index => stable argsort).
    for (int k = 2; k <= GN; k <<= 1) {
        for (int j = k >> 1; j > 0; j >>= 1) {
            __syncthreads();
            int ixj = i ^ j;
            if (ixj > i) {
                unsigned long long a = s_key[i], b = s_key[ixj];
                bool asc = ((i & k) == 0);
                if ((a > b) == asc) { s_key[i] = b; s_key[ixj] = a; }
            }
        }
    }
    __syncthreads();

    // Order-preserving compaction of valid entries into packed global arrays.
    int src = (int)(s_key[i] & 0xffffffffu);
    bool keep = (s_valid[src] != 0);
    unsigned bm = __ballot_sync(0xffffffffu, keep);
    int lane = i & 31, w = i >> 5;
    if (lane == 0) s_wcnt[w] = __popc(bm);
    __syncthreads();
    int woff = 0;
#pragma unroll
    for (int ww = 0; ww < 16; ww++)
        if (ww < w) woff += s_wcnt[ww];
    if (keep) {
        int p = woff + __popc(bm & ((1u << lane) - 1u));
        float c00 = s_c00[src], c11 = s_c11[src];
        g_pk1[p] = make_float4(s_gx[src], s_gy[src], c00, c11);
        g_pk2[p] = make_float4(s_op[src], s_dep[src],
                               __int_as_float(src), sqrtf(36.0f / c00));
    }
    if (i == 0) {
        int tot = 0;
#pragma unroll
        for (int ww = 0; ww < 16; ww++) tot += s_wcnt[ww];
        g_cnt = tot;
        s_tot = tot;
    }
    __syncthreads();

    // Row binning: thread r builds depth-ordered list for tile row r.
    if (i < NROWS) {
        const int M = s_tot;
        const float ry0 = (float)(i * TSY);
        const float ry1 = (float)(i * TSY + TSY - 1);
        int c = 0;
        for (int g = 0; g < M; g++) {
            float gy  = g_pk1[g].y;
            float c11 = g_pk1[g].w;
            float ry  = sqrtf(36.0f / c11);
            if (gy + ry >= ry0 && gy - ry <= ry1)
                g_rowlist[i][c++] = g;
        }
        g_rowcnt[i] = c;
    }
}

// ---------------------------------------------------------------------------
// Kernel 2: per-tile x-cull (from row bin) + branchless depth-ordered
// compositing. Block = 256 threads = 64 pixels (16x4) x 4 channel groups.
// ---------------------------------------------------------------------------
__global__ __launch_bounds__(256, 3) void render_kernel(
    const float* __restrict__ spec,   // [N, C]
    const float* __restrict__ tone,   // [C]
    float* __restrict__ out)          // [C*HW + HW + HW]
{
    __shared__ float4 s1[GN];         // gx, gy, c00, c11
    __shared__ float4 s2[GN];         // op, depth, sid, rx
    __shared__ float  s_tone[GC];
    __shared__ int    s_cnt, s_wcnt[8];

    const int tid = threadIdx.x;
    if (tid < GC) s_tone[tid] = tone[tid];
    if (tid == 0) s_cnt = 0;

    const int row  = blockIdx.y;
    const int Mrow = g_rowcnt[row];
    const int x0 = blockIdx.x * TSX, y0 = row * TSY;
    const float fx0 = (float)x0, fx1 = (float)(x0 + TSX - 1);
    __syncthreads();

    // Order-preserving x-cull from this row's list (chunks of 256).
    for (int base = 0; base < Mrow; base += 256) {
        int li = base + tid;
        bool keep = false;
        float4 f1, f2;
        if (li < Mrow) {
            int gi = g_rowlist[row][li];
            f1 = g_pk1[gi];
            f2 = g_pk2[gi];
            keep = (f1.x + f2.w >= fx0) && (f1.x - f2.w <= fx1);
        }
        unsigned bm = __ballot_sync(0xffffffffu, keep);
        int lane = tid & 31, w = tid >> 5;
        if (lane == 0) s_wcnt[w] = __popc(bm);
        __syncthreads();
        int woff = 0;
#pragma unroll
        for (int ww = 0; ww < 8; ww++)
            if (ww < w) woff += s_wcnt[ww];
        if (keep) {
            int p = s_cnt + woff + __popc(bm & ((1u << lane) - 1u));
            s1[p] = f1;
            s2[p] = f2;
        }
        __syncthreads();
        if (tid == 0) {
            int tt = 0;
#pragma unroll
            for (int ww = 0; ww < 8; ww++) tt += s_wcnt[ww];
            s_cnt += tt;
        }
        __syncthreads();
    }
    const int cnt = s_cnt;

    const int cg  = tid >> 6;          // channel group 0..3 (warp-uniform)
    const int pix = tid & 63;          // pixel within 16x4 tile
    const int px  = x0 + (pix & 15);
    const int py  = y0 + (pix >> 4);
    const float fpx = (float)px, fpy = (float)py;
    const int cbase = cg * 32;         // 0,32,64,96

    float A = 0.0f, D = 0.0f;
    float acc[32];
#pragma unroll
    for (int c = 0; c < 32; c++) acc[c] = 0.0f;

    // Branchless depth-ordered compositing (uniform LDS.128 broadcasts;
    // exp underflows to 0 for far gaussians, matching reference w/o cutoff).
    for (int k = 0; k < cnt; k++) {
        float4 P1 = s1[k];
        float4 P2 = s2[k];
        float dx = fpx - P1.x;
        float dy = fpy - P1.y;
        float m  = dx * dx * P1.z + dy * dy * P1.w;
        float alpha = P2.x * __expf(-0.5f * m) * (1.0f - A);
        A += alpha;
        D += P2.y * alpha;
        const int id = __float_as_int(P2.z);
        const float4* sp = (const float4*)(spec + (size_t)id * GC + cbase);
        if (cg < 3) {
#pragma unroll
            for (int q = 0; q < 8; q++) {
                float4 v = __ldg(sp + q);
                acc[4 * q + 0] += alpha * v.x;
                acc[4 * q + 1] += alpha * v.y;
                acc[4 * q + 2] += alpha * v.z;
                acc[4 * q + 3] += alpha * v.w;
            }
        } else {
#pragma unroll
            for (int q = 0; q < 6; q++) {
                float4 v = __ldg(sp + q);
                acc[4 * q + 0] += alpha * v.x;
                acc[4 * q + 1] += alpha * v.y;
                acc[4 * q + 2] += alpha * v.z;
                acc[4 * q + 3] += alpha * v.w;
            }
        }
    }

    if (px < GW) {   // py always < GH (324 = 81*4)
        const int p = py * GW + px;
        const float bg = 1.0f - A;   // BG = 1.0
        const int nch = (cg < 3) ? 32 : 24;
#pragma unroll 8
        for (int c = 0; c < nch; c++)
            out[(size_t)(cbase + c) * GHW + p] = (acc[c] + bg) * s_tone[cbase + c];
        if (cg == 0) {
            out[(size_t)GC * GHW + p] = D;              // depth image
            out[(size_t)GC * GHW + GHW + p] = A;        // A_final
        }
    }
}

// ---------------------------------------------------------------------------
// Inputs (metadata order): positions[N,3], rotations[N,4](unused), scales[N,3],
// opacities[N], spectral_features[N,C], tone_mapping[C], intrinsics[3,3],
// extrinsics[4,4]. Output: concat(spectral[C,H,W], depth[H,W], A[H,W]) fp32.
// ---------------------------------------------------------------------------
extern "C" void kernel_launch(void* const* d_in, const int* in_sizes, int n_in,
                              void* d_out, int out_size)
{
    const float* positions  = (const float*)d_in[0];
    const float* scales     = (const float*)d_in[2];
    const float* opacities  = (const float*)d_in[3];
    const float* spectral   = (const float*)d_in[4];
    const float* tone       = (const float*)d_in[5];
    const float* intr       = (const float*)d_in[6];
    const float* extr       = (const float*)d_in[7];
    float* out = (float*)d_out;

    prep_kernel<<<1, GN>>>(positions, scales, opacities, intr, extr);

    dim3 grid((GW + TSX - 1) / TSX, NROWS);
    render_kernel<<<grid, 256>>>(spectral, tone, out);
}

// round 6
// speedup vs baseline: 1.4007x; 1.4007x over previous
#include <cuda_runtime.h>
#include <cuda_bf16.h>
#include <stdint.h>

#define GN 512
#define GW 332
#define GH 324
#define GHW (GW * GH)
#define GC 120
#define TSX 16
#define TSY 4
#define NROWS 81   // GH / TSY

// packed compact gaussian params (depth-sorted, valid only)
__device__ float4 g_pk1[GN];            // gx, gy, c00, c11
__device__ float4 g_pk2[GN];            // op, depth, sid (float bits), rx
__device__ int    g_cnt;
__device__ int    g_rowcnt[NROWS];
__device__ float4 g_row1[NROWS][GN];    // per-row depth-ordered packed params
__device__ float4 g_row2[NROWS][GN];

static __device__ __forceinline__ unsigned order_float(float f) {
    unsigned u = __float_as_uint(f);
    return (u & 0x80000000u) ? ~u : (u | 0x80000000u);
}

// ---------------------------------------------------------------------------
// Kernel 1: project, validity, cinv, stable depth sort, compact.
// One block, 512 threads.
// ---------------------------------------------------------------------------
__global__ __launch_bounds__(GN) void prep_kernel(
    const float* __restrict__ pos,     // [N,3]
    const float* __restrict__ scales,  // [N,3]
    const float* __restrict__ ops,     // [N]
    const float* __restrict__ K,       // [3,3]
    const float* __restrict__ E)       // [4,4]
{
    __shared__ float s_gx[GN], s_gy[GN], s_c00[GN], s_c11[GN], s_op[GN], s_dep[GN];
    __shared__ unsigned char s_valid[GN];
    __shared__ unsigned long long s_key[GN];
    __shared__ int s_wcnt[16];

    const int i = threadIdx.x;

    float p0 = pos[3 * i + 0], p1 = pos[3 * i + 1], p2 = pos[3 * i + 2];
    float cx = E[0] * p0 + E[1] * p1 + E[2]  * p2 + E[3];
    float cy = E[4] * p0 + E[5] * p1 + E[6]  * p2 + E[7];
    float cz = E[8] * p0 + E[9] * p1 + E[10] * p2 + E[11];
    float prx = K[0] * cx + K[1] * cy + K[2] * cz;
    float pry = K[3] * cx + K[4] * cy + K[5] * cz;
    float prz = K[6] * cx + K[7] * cy + K[8] * cz;
    float sx = prx / (prz + 1e-6f);
    float sy = pry / (prz + 1e-6f);
    float d  = cz;

    bool valid = (d > 0.01f) && (d < 100.0f) &&
                 (sx > -100.0f) && (sx < (float)GW + 100.0f) &&
                 (sy > -100.0f) && (sy < (float)GH + 100.0f);

    float s0 = scales[3 * i + 0], s1 = scales[3 * i + 1];
    s_gx[i]  = sx;
    s_gy[i]  = sy;
    s_c00[i] = 1.0f / (s0 * s0 + 1e-4f);
    s_c11[i] = 1.0f / (s1 * s1 + 1e-4f);
    s_op[i]  = ops[i];
    s_dep[i] = d;
    s_valid[i] = valid ? 1 : 0;
    s_key[i] = ((unsigned long long)order_float(d) << 32) | (unsigned)i;
    __syncthreads();

    // Bitonic sort 512 keys ascending (depth, then index => stable argsort).
    for (int k = 2; k <= GN; k <<= 1) {
        for (int j = k >> 1; j > 0; j >>= 1) {
            __syncthreads();
            int ixj = i ^ j;
            if (ixj > i) {
                unsigned long long a = s_key[i], b = s_key[ixj];
                bool asc = ((i & k) == 0);
                if ((a > b) == asc) { s_key[i] = b; s_key[ixj] = a; }
            }
        }
    }
    __syncthreads();

    // Order-preserving compaction of valid entries into packed global arrays.
    int src = (int)(s_key[i] & 0xffffffffu);
    bool keep = (s_valid[src] != 0);
    unsigned bm = __ballot_sync(0xffffffffu, keep);
    int lane = i & 31, w = i >> 5;
    if (lane == 0) s_wcnt[w] = __popc(bm);
    __syncthreads();
    int woff = 0;
#pragma unroll
    for (int ww = 0; ww < 16; ww++)
        if (ww < w) woff += s_wcnt[ww];
    if (keep) {
        int p = woff + __popc(bm & ((1u << lane) - 1u));
        float c00 = s_c00[src], c11 = s_c11[src];
        g_pk1[p] = make_float4(s_gx[src], s_gy[src], c00, c11);
        g_pk2[p] = make_float4(s_op[src], s_dep[src],
                               __int_as_float(src), sqrtf(36.0f / c00));
    }
    if (i == 0) {
        int tot = 0;
#pragma unroll
        for (int ww = 0; ww < 16; ww++) tot += s_wcnt[ww];
        g_cnt = tot;
    }
}

// ---------------------------------------------------------------------------
// Kernel 1b: row binning. One block per tile row; order-preserving ballot
// compaction of the sorted list into packed per-row arrays (coalesced).
// ---------------------------------------------------------------------------
__global__ __launch_bounds__(256) void bin_kernel()
{
    __shared__ int s_cnt, s_wcnt[8];
    const int tid = threadIdx.x;
    const int row = blockIdx.x;
    if (tid == 0) s_cnt = 0;
    const int M = g_cnt;
    const float ry0 = (float)(row * TSY);
    const float ry1 = (float)(row * TSY + TSY - 1);
    __syncthreads();

    for (int base = 0; base < M; base += 256) {
        int li = base + tid;
        bool keep = false;
        float4 f1, f2;
        if (li < M) {
            f1 = g_pk1[li];
            f2 = g_pk2[li];
            float ry = sqrtf(36.0f / f1.w);
            keep = (f1.y + ry >= ry0) && (f1.y - ry <= ry1);
        }
        unsigned bm = __ballot_sync(0xffffffffu, keep);
        int lane = tid & 31, w = tid >> 5;
        if (lane == 0) s_wcnt[w] = __popc(bm);
        __syncthreads();
        int woff = 0;
#pragma unroll
        for (int ww = 0; ww < 8; ww++)
            if (ww < w) woff += s_wcnt[ww];
        if (keep) {
            int p = s_cnt + woff + __popc(bm & ((1u << lane) - 1u));
            g_row1[row][p] = f1;
            g_row2[row][p] = f2;
        }
        __syncthreads();
        if (tid == 0) {
            int tt = 0;
#pragma unroll
            for (int ww = 0; ww < 8; ww++) tt += s_wcnt[ww];
            s_cnt += tt;
        }
        __syncthreads();
    }
    if (tid == 0) g_rowcnt[row] = s_cnt;
}

// ---------------------------------------------------------------------------
// Kernel 2: per-tile x-cull (from row bin) + branchless depth-ordered
// compositing, unrolled x2. Block = 256 = 64 px (16x4) x 4 channel groups.
// ---------------------------------------------------------------------------
__global__ __launch_bounds__(256, 3) void render_kernel(
    const float* __restrict__ spec,   // [N, C]
    const float* __restrict__ tone,   // [C]
    float* __restrict__ out)          // [C*HW + HW + HW]
{
    __shared__ float4 s1[GN];         // gx, gy, c00, c11
    __shared__ float4 s2[GN];         // op, depth, sid, rx
    __shared__ float  s_tone[GC];
    __shared__ int    s_cnt, s_wcnt[8];

    const int tid = threadIdx.x;
    if (tid < GC) s_tone[tid] = tone[tid];
    if (tid == 0) s_cnt = 0;

    const int row  = blockIdx.y;
    const int Mrow = g_rowcnt[row];
    const int x0 = blockIdx.x * TSX, y0 = row * TSY;
    const float fx0 = (float)x0, fx1 = (float)(x0 + TSX - 1);
    __syncthreads();

    // Order-preserving x-cull from this row's packed list (chunks of 256).
    for (int base = 0; base < Mrow; base += 256) {
        int li = base + tid;
        bool keep = false;
        float4 f1, f2;
        if (li < Mrow) {
            f1 = g_row1[row][li];
            f2 = g_row2[row][li];
            keep = (f1.x + f2.w >= fx0) && (f1.x - f2.w <= fx1);
        }
        unsigned bm = __ballot_sync(0xffffffffu, keep);
        int lane = tid & 31, w = tid >> 5;
        if (lane == 0) s_wcnt[w] = __popc(bm);
        __syncthreads();
        int woff = 0;
#pragma unroll
        for (int ww = 0; ww < 8; ww++)
            if (ww < w) woff += s_wcnt[ww];
        if (keep) {
            int p = s_cnt + woff + __popc(bm & ((1u << lane) - 1u));
            s1[p] = f1;
            s2[p] = f2;
        }
        __syncthreads();
        if (tid == 0) {
            int tt = 0;
#pragma unroll
            for (int ww = 0; ww < 8; ww++) tt += s_wcnt[ww];
            s_cnt += tt;
        }
        __syncthreads();
    }
    const int cnt = s_cnt;

    const int cg  = tid >> 6;          // channel group 0..3 (warp-uniform)
    const int pix = tid & 63;          // pixel within 16x4 tile
    const int px  = x0 + (pix & 15);
    const int py  = y0 + (pix >> 4);
    const float fpx = (float)px, fpy = (float)py;
    const int cbase = cg * 32;         // 0,32,64,96
    const int nq = (cg < 3) ? 8 : 6;   // warp-uniform

    float A = 0.0f, D = 0.0f;
    float acc[32];
#pragma unroll
    for (int c = 0; c < 32; c++) acc[c] = 0.0f;

    // Branchless depth-ordered compositing, 2 gaussians per step.
    // Only A carries a loop dependency (2 flops); exp/LDS/LDG of both
    // gaussians are independent -> doubled MLP per dependency step.
    int k = 0;
    for (; k + 2 <= cnt; k += 2) {
        float4 Pa1 = s1[k],     Pa2 = s2[k];
        float4 Pb1 = s1[k + 1], Pb2 = s2[k + 1];
        float dxa = fpx - Pa1.x, dya = fpy - Pa1.y;
        float dxb = fpx - Pb1.x, dyb = fpy - Pb1.y;
        float ma = dxa * dxa * Pa1.z + dya * dya * Pa1.w;
        float mb = dxb * dxb * Pb1.z + dyb * dyb * Pb1.w;
        float ea = __expf(-0.5f * ma);
        float eb = __expf(-0.5f * mb);
        float aa = Pa2.x * ea * (1.0f - A);
        float A1 = A + aa;
        float ab = Pb2.x * eb * (1.0f - A1);
        A = A1 + ab;
        D += Pa2.y * aa + Pb2.y * ab;
        const float4* spa = (const float4*)(spec + (size_t)__float_as_int(Pa2.z) * GC + cbase);
        const float4* spb = (const float4*)(spec + (size_t)__float_as_int(Pb2.z) * GC + cbase);
        if (cg < 3) {
#pragma unroll
            for (int q = 0; q < 8; q++) {
                float4 va = __ldg(spa + q);
                float4 vb = __ldg(spb + q);
                acc[4 * q + 0] += aa * va.x + ab * vb.x;
                acc[4 * q + 1] += aa * va.y + ab * vb.y;
                acc[4 * q + 2] += aa * va.z + ab * vb.z;
                acc[4 * q + 3] += aa * va.w + ab * vb.w;
            }
        } else {
#pragma unroll
            for (int q = 0; q < 6; q++) {
                float4 va = __ldg(spa + q);
                float4 vb = __ldg(spb + q);
                acc[4 * q + 0] += aa * va.x + ab * vb.x;
                acc[4 * q + 1] += aa * va.y + ab * vb.y;
                acc[4 * q + 2] += aa * va.z + ab * vb.z;
                acc[4 * q + 3] += aa * va.w + ab * vb.w;
            }
        }
    }
    if (k < cnt) {   // tail
        float4 P1 = s1[k];
        float4 P2 = s2[k];
        float dx = fpx - P1.x, dy = fpy - P1.y;
        float m  = dx * dx * P1.z + dy * dy * P1.w;
        float alpha = P2.x * __expf(-0.5f * m) * (1.0f - A);
        A += alpha;
        D += P2.y * alpha;
        const float4* sp = (const float4*)(spec + (size_t)__float_as_int(P2.z) * GC + cbase);
#pragma unroll 8
        for (int q = 0; q < nq; q++) {
            float4 v = __ldg(sp + q);
            acc[4 * q + 0] += alpha * v.x;
            acc[4 * q + 1] += alpha * v.y;
            acc[4 * q + 2] += alpha * v.z;
            acc[4 * q + 3] += alpha * v.w;
        }
    }

    if (px < GW) {   // py always < GH (324 = 81*4)
        const int p = py * GW + px;
        const float bg = 1.0f - A;   // BG = 1.0
        const int nch = (cg < 3) ? 32 : 24;
#pragma unroll 8
        for (int c = 0; c < nch; c++)
            out[(size_t)(cbase + c) * GHW + p] = (acc[c] + bg) * s_tone[cbase + c];
        if (cg == 0) {
            out[(size_t)GC * GHW + p] = D;              // depth image
            out[(size_t)GC * GHW + GHW + p] = A;        // A_final
        }
    }
}

// ---------------------------------------------------------------------------
// Inputs (metadata order): positions[N,3], rotations[N,4](unused), scales[N,3],
// opacities[N], spectral_features[N,C], tone_mapping[C], intrinsics[3,3],
// extrinsics[4,4]. Output: concat(spectral[C,H,W], depth[H,W], A[H,W]) fp32.
// ---------------------------------------------------------------------------
extern "C" void kernel_launch(void* const* d_in, const int* in_sizes, int n_in,
                              void* d_out, int out_size)
{
    const float* positions  = (const float*)d_in[0];
    const float* scales     = (const float*)d_in[2];
    const float* opacities  = (const float*)d_in[3];
    const float* spectral   = (const float*)d_in[4];
    const float* tone       = (const float*)d_in[5];
    const float* intr       = (const float*)d_in[6];
    const float* extr       = (const float*)d_in[7];
    float* out = (float*)d_out;

    prep_kernel<<<1, GN>>>(positions, scales, opacities, intr, extr);
    bin_kernel<<<NROWS, 256>>>();

    dim3 grid((GW + TSX - 1) / TSX, NROWS);
    render_kernel<<<grid, 256>>>(spectral, tone, out);
}